// round 17
// baseline (speedup 1.0000x reference)
#include <cuda_runtime.h>
#include <cuda_bf16.h>
#include <math.h>

#define FULLMASK 0xffffffffu
#define F_ 16
#define NPTS 2000
#define NL 500
#define NS 1500
#define D 32
#define NROWS (F_ * NPTS)   // 32000
#define NRG (NROWS / 8)     // 4000 row-groups of 8 rows
#define NRG2 (NROWS / 16)   // 2000 row-groups of 16 rows (2 rows/warp)
#define NRG4 (NROWS / 32)   // 1000 row-groups of 32 rows (4 rows/warp)
#define CAP 128
#define SLOPE 0.2f

#define GRID_P 592          // persistent grid (4 blocks/SM * 148)

// ---------------- scratch (static device globals; no allocation) ----------------
__device__ float g_buf[NROWS * D];          // 4 MB
__device__ float s_l_buf[NROWS];
__device__ float s_r_buf[NROWS];
__device__ float E_buf[F_ * F_ * NPTS];     // 2 MB : E[b][r][j] = lrelu(s_l[b,j]+s_r[r,j])
__device__ float w4T_buf[NPTS * D];         // 256 KB
__device__ float h_buf[NROWS * D];          // 4 MB
__device__ float st_buf[NROWS * D];         // 4 MB
__device__ float csum_buf[F_ * D];
__device__ unsigned short col_buf[(size_t)NROWS * CAP];  // 8 MB (rows 256B-aligned)
__device__ int cnt_buf[NROWS];

__device__ __forceinline__ float lrelu(float x) { return x > 0.f ? x : SLOPE * x; }

// ---------------- K1: g = x @ w3^T + b3 ; s_l ; s_r  (persistent, 4 rows/warp) ----
__global__ void __launch_bounds__(256) k1_gsl(const float* __restrict__ state,
                                              const float* __restrict__ left,
                                              const float* __restrict__ w3,
                                              const float* __restrict__ b3,
                                              const float* __restrict__ attn_w) {
    __shared__ float w3T[D * D];   // w3T[d*32+o] = w3[o][d]
    __shared__ float sb3[D], sal[D], sar[D];
    int t = threadIdx.x;
    for (int idx = t; idx < D * D; idx += 256) {
        int d = idx >> 5, o = idx & 31;
        w3T[idx] = w3[o * D + d];
    }
    if (t < D) { sb3[t] = b3[t]; sal[t] = attn_w[t]; sar[t] = attn_w[D + t]; }
    __syncthreads();

    int warp = t >> 5, lane = t & 31;
    for (int rg = blockIdx.x; rg < NRG4; rg += GRID_P) {
        int row0 = rg * 32 + warp * 4;
        float x0, x1, x2, x3;
#pragma unroll
        for (int rr = 0; rr < 4; rr++) {
            int row = row0 + rr;
            int b = row / NPTS, i = row % NPTS;
            float xv;
            if (i < NL) xv = left[((size_t)b * NL + i) * D + lane];
            else        xv = state[((size_t)b * NS + (i - NL)) * D + lane];
            if (rr == 0) x0 = xv; else if (rr == 1) x1 = xv;
            else if (rr == 2) x2 = xv; else x3 = xv;
        }

        float bb = sb3[lane];
        float a0 = bb, a1 = bb, a2 = bb, a3 = bb;
#pragma unroll
        for (int d = 0; d < D; d++) {
            float w = w3T[d * D + lane];
            a0 = fmaf(__shfl_sync(FULLMASK, x0, d), w, a0);
            a1 = fmaf(__shfl_sync(FULLMASK, x1, d), w, a1);
            a2 = fmaf(__shfl_sync(FULLMASK, x2, d), w, a2);
            a3 = fmaf(__shfl_sync(FULLMASK, x3, d), w, a3);
        }
        g_buf[(size_t)(row0 + 0) * D + lane] = a0;
        g_buf[(size_t)(row0 + 1) * D + lane] = a1;
        g_buf[(size_t)(row0 + 2) * D + lane] = a2;
        g_buf[(size_t)(row0 + 3) * D + lane] = a3;

        float al = sal[lane], ar = sar[lane];
        float sl0 = a0 * al, sr0 = a0 * ar;
        float sl1 = a1 * al, sr1 = a1 * ar;
        float sl2 = a2 * al, sr2 = a2 * ar;
        float sl3 = a3 * al, sr3 = a3 * ar;
#pragma unroll
        for (int off = 16; off; off >>= 1) {
            sl0 += __shfl_xor_sync(FULLMASK, sl0, off);
            sr0 += __shfl_xor_sync(FULLMASK, sr0, off);
            sl1 += __shfl_xor_sync(FULLMASK, sl1, off);
            sr1 += __shfl_xor_sync(FULLMASK, sr1, off);
            sl2 += __shfl_xor_sync(FULLMASK, sl2, off);
            sr2 += __shfl_xor_sync(FULLMASK, sr2, off);
            sl3 += __shfl_xor_sync(FULLMASK, sl3, off);
            sr3 += __shfl_xor_sync(FULLMASK, sr3, off);
        }
        if (lane == 0) {
            s_l_buf[row0 + 0] = sl0; s_r_buf[row0 + 0] = sr0;
            s_l_buf[row0 + 1] = sl1; s_r_buf[row0 + 1] = sr1;
            s_l_buf[row0 + 2] = sl2; s_r_buf[row0 + 2] = sr2;
            s_l_buf[row0 + 3] = sl3; s_r_buf[row0 + 3] = sr3;
        }
    }
}

// ---------------- K1b: E table + w4 transpose ----------------
__global__ void k1b_prep(const float* __restrict__ w4) {
    int tid = blockIdx.x * blockDim.x + threadIdx.x;
    int stride = gridDim.x * blockDim.x;
    for (int idx = tid; idx < F_ * F_ * NPTS; idx += stride) {
        int j = idx % NPTS;
        int br = idx / NPTS;
        int r = br % F_, b = br / F_;
        float v = s_l_buf[b * NPTS + j] + s_r_buf[r * NPTS + j];
        E_buf[idx] = lrelu(v);
    }
    for (int idx = tid; idx < NPTS * D; idx += stride) {
        int o = idx & 31, j = idx >> 5;
        w4T_buf[idx] = w4[o * NPTS + j];   // w4T[j][o]
    }
}

// ---------------- K1c: zero csum (also positions k2_fused at profiled launch idx 3) ----
__global__ void k1c_zero() {
    int idx = blockIdx.x * blockDim.x + threadIdx.x;
    if (idx < F_ * D) csum_buf[idx] = 0.f;
}

// ---------------- K2 (fused, persistent): coalesced stream scan -> unordered
// index compaction (no ballots) -> sparse h -> exp-sum atomic ----------------
__global__ void __launch_bounds__(256) k2_fused(const float* __restrict__ inputad,
                                                const float* __restrict__ b4) {
    __shared__ unsigned short scol[8][CAP];
    __shared__ float sexp[8][32];
    int t = threadIdx.x, warp = t >> 5, lane = t & 31;
    float sb4 = b4[lane];

    for (int rg = blockIdx.x; rg < NRG; rg += GRID_P) {
        int row = rg * 8 + warp;
        int b = row / NPTS, i = row % NPTS;
        int r = i & 15;                               // (b*2000+i) % 16 == i % 16
        const float4* __restrict__ adrow = (const float4*)(inputad + (size_t)row * NPTS);

        // ---- phase 1: coalesced loads, build 64-bit mask ----
        unsigned long long mask = 0ull;
#pragma unroll
        for (int half = 0; half < 2; half++) {
            float4 v[8];
#pragma unroll
            for (int u = 0; u < 8; u++) {
                int f = (half * 8 + u) * 32 + lane;   // coalesced: warp covers 512B
                v[u] = make_float4(0.f, 0.f, 0.f, 0.f);
                if (f < 500) v[u] = __ldg(adrow + f);
            }
#pragma unroll
            for (int u = 0; u < 8; u++) {
                int bb = (half * 8 + u) * 4;
                unsigned long long m = 0;
                if (v[u].x != 0.f) m |= 1ull;
                if (v[u].y != 0.f) m |= 2ull;
                if (v[u].z != 0.f) m |= 4ull;
                if (v[u].w != 0.f) m |= 8ull;
                mask |= m << bb;
            }
        }

        // ---- phase 2: warp exclusive scan of per-thread counts ----
        int myc = __popcll(mask);
        int incl = myc;
#pragma unroll
        for (int off = 1; off < 32; off <<= 1) {
            int n = __shfl_up_sync(FULLMASK, incl, off);
            if (lane >= off) incl += n;
        }
        int excl = incl - myc;
        int cnt = __shfl_sync(FULLMASK, incl, 31);
        int cc = cnt < CAP ? cnt : CAP;

        // ---- phase 3: write indices (unordered across lanes) to shared ----
        {
            int pos = excl;
            unsigned long long m = mask;
            while (m) {
                int p = __ffsll(m) - 1;
                m &= m - 1;
                int col = ((p >> 2) << 7) + (lane << 2) + (p & 3);
                if (pos < CAP) scol[warp][pos] = (unsigned short)col;
                pos++;
            }
        }
        __syncwarp();

        // spill to gmem for k4 (coalesced)
        {
            unsigned short* crow = col_buf + (size_t)row * CAP;
            for (int k = lane; k < cc; k += 32) crow[k] = scol[warp][k];
            if (lane == 0) cnt_buf[row] = cnt;
        }

        // ---- phase 4: sparse h accumulation (lane = output channel) ----
        const float* __restrict__ Erow = E_buf + (b * F_ + r) * NPTS;
        float a0 = 0.f, a1 = 0.f, a2 = 0.f, a3 = 0.f;
        int k = 0;
        for (; k + 4 <= cc; k += 4) {
            int j0 = scol[warp][k], j1 = scol[warp][k + 1];
            int j2 = scol[warp][k + 2], j3 = scol[warp][k + 3];
            a0 = fmaf(Erow[j0], w4T_buf[j0 * D + lane], a0);
            a1 = fmaf(Erow[j1], w4T_buf[j1 * D + lane], a1);
            a2 = fmaf(Erow[j2], w4T_buf[j2 * D + lane], a2);
            a3 = fmaf(Erow[j3], w4T_buf[j3 * D + lane], a3);
        }
        for (; k < cc; k++) {
            int j = scol[warp][k];
            a0 = fmaf(Erow[j], w4T_buf[j * D + lane], a0);
        }
        float h = lrelu((a0 + a1) + (a2 + a3) + sb4);
        h_buf[row * D + lane] = h;

        // ---- phase 5: block exp-sum -> atomic (8 rows share b: 2000 % 8 == 0) ----
        sexp[warp][lane] = __expf(h);
        __syncthreads();
        if (warp == 0) {
            float s = sexp[0][lane];
#pragma unroll
            for (int w = 1; w < 8; w++) s += sexp[w][lane];
            atomicAdd(&csum_buf[b * D + lane], s);
        }
        __syncthreads();
    }
}

// ---------------- K3b: st = (softmax(h)*g) @ w1^T + b1  (persistent, 4 rows/warp) ----
__global__ void __launch_bounds__(256) k3b_st(const float* __restrict__ w1,
                                              const float* __restrict__ b1) {
    __shared__ float w1T[D * D];
    __shared__ float sb1[D];
    int t = threadIdx.x;
    for (int idx = t; idx < D * D; idx += 256) {
        int d = idx >> 5, p = idx & 31;
        w1T[idx] = w1[p * D + d];
    }
    if (t < D) sb1[t] = b1[t];
    __syncthreads();

    int warp = t >> 5, lane = t & 31;
    for (int rg = blockIdx.x; rg < NRG4; rg += GRID_P) {
        int row0 = rg * 32 + warp * 4;
        int b = row0 / NPTS;                          // 4 consecutive rows share b (2000%4==0)
        float cs = csum_buf[b * D + lane];
        float t0 = __expf(h_buf[(size_t)(row0 + 0) * D + lane]) / cs * g_buf[(size_t)(row0 + 0) * D + lane];
        float t1 = __expf(h_buf[(size_t)(row0 + 1) * D + lane]) / cs * g_buf[(size_t)(row0 + 1) * D + lane];
        float t2 = __expf(h_buf[(size_t)(row0 + 2) * D + lane]) / cs * g_buf[(size_t)(row0 + 2) * D + lane];
        float t3 = __expf(h_buf[(size_t)(row0 + 3) * D + lane]) / cs * g_buf[(size_t)(row0 + 3) * D + lane];

        float bb = sb1[lane];
        float a0 = bb, a1 = bb, a2 = bb, a3 = bb;
#pragma unroll
        for (int d = 0; d < D; d++) {
            float w = w1T[d * D + lane];
            a0 = fmaf(__shfl_sync(FULLMASK, t0, d), w, a0);
            a1 = fmaf(__shfl_sync(FULLMASK, t1, d), w, a1);
            a2 = fmaf(__shfl_sync(FULLMASK, t2, d), w, a2);
            a3 = fmaf(__shfl_sync(FULLMASK, t3, d), w, a3);
        }
        st_buf[(size_t)(row0 + 0) * D + lane] = a0;
        st_buf[(size_t)(row0 + 1) * D + lane] = a1;
        st_buf[(size_t)(row0 + 2) * D + lane] = a2;
        st_buf[(size_t)(row0 + 3) * D + lane] = a3;
    }
}

// ---------------- K4: agg gather + layernorm + gates + final matmul ----------------
// 2 rows per warp: interleaved gathers (up to 16 outstanding loads) and shared
// weight LDS amortized across both rows.
__global__ void __launch_bounds__(256) k4_final(const float* __restrict__ w_ih,
                                                const float* __restrict__ b_ih,
                                                const float* __restrict__ b_hh,
                                                const float* __restrict__ ln_g,
                                                const float* __restrict__ ln_b,
                                                const float* __restrict__ w2,
                                                const float* __restrict__ b2,
                                                float* __restrict__ out) {
    __shared__ float ihT[D * 128];   // ihT[d*128+k] = w_ih[k][d]
    __shared__ float w2T[D * D];     // w2T[d*32+q] = w2[q][d]
    __shared__ float sbi[96], sg[D], sb[D], sb2[D];
    int t = threadIdx.x;
    for (int idx = t; idx < D * 128; idx += 256) {
        int d = idx >> 7, k = idx & 127;
        ihT[idx] = w_ih[k * D + d];
    }
    for (int idx = t; idx < D * D; idx += 256) {
        int d = idx >> 5, q = idx & 31;
        w2T[idx] = w2[q * D + d];
    }
    if (t < 96) sbi[t] = b_ih[t] + b_hh[t];
    if (t < D) { sg[t] = ln_g[t]; sb[t] = ln_b[t]; sb2[t] = b2[t]; }
    __syncthreads();

    int warp = t >> 5, lane = t & 31;
    for (int rg = blockIdx.x; rg < NRG2; rg += GRID_P) {
        int rowA = rg * 16 + warp * 2;
        int rowB = rowA + 1;
        int b = rowA / NPTS;                          // both rows share b (2000 even)
        const unsigned short* __restrict__ crA = col_buf + (size_t)rowA * CAP;
        const unsigned short* __restrict__ crB = col_buf + (size_t)rowB * CAP;
        int cA = cnt_buf[rowA]; if (cA > CAP) cA = CAP;
        int cB = cnt_buf[rowB]; if (cB > CAP) cB = CAP;
        const float* __restrict__ stb = st_buf + (size_t)b * NPTS * D;

        // interleaved gather: 4 indices per row per step = 8 loads in flight x2 rows
        float A0 = 0.f, A1 = 0.f, A2 = 0.f, A3 = 0.f;
        float B0 = 0.f, B1 = 0.f, B2 = 0.f, B3 = 0.f;
        int cmin = cA < cB ? cA : cB;
        int k2 = 0;
        for (; k2 + 4 <= cmin; k2 += 4) {
            int a0 = crA[k2], a1 = crA[k2 + 1], a2 = crA[k2 + 2], a3 = crA[k2 + 3];
            int b0 = crB[k2], b1 = crB[k2 + 1], b2 = crB[k2 + 2], b3 = crB[k2 + 3];
            A0 += stb[a0 * D + lane];
            B0 += stb[b0 * D + lane];
            A1 += stb[a1 * D + lane];
            B1 += stb[b1 * D + lane];
            A2 += stb[a2 * D + lane];
            B2 += stb[b2 * D + lane];
            A3 += stb[a3 * D + lane];
            B3 += stb[b3 * D + lane];
        }
        // tails
        int ka = k2;
        for (; ka + 4 <= cA; ka += 4) {
            int a0 = crA[ka], a1 = crA[ka + 1], a2 = crA[ka + 2], a3 = crA[ka + 3];
            A0 += stb[a0 * D + lane];
            A1 += stb[a1 * D + lane];
            A2 += stb[a2 * D + lane];
            A3 += stb[a3 * D + lane];
        }
        for (; ka < cA; ka++) A0 += stb[crA[ka] * D + lane];
        int kb = k2;
        for (; kb + 4 <= cB; kb += 4) {
            int b0 = crB[kb], b1 = crB[kb + 1], b2 = crB[kb + 2], b3 = crB[kb + 3];
            B0 += stb[b0 * D + lane];
            B1 += stb[b1 * D + lane];
            B2 += stb[b2 * D + lane];
            B3 += stb[b3 * D + lane];
        }
        for (; kb < cB; kb++) B0 += stb[crB[kb] * D + lane];
        float aggA = (A0 + A1) + (A2 + A3);
        float aggB = (B0 + B1) + (B2 + B3);

        float stA = st_buf[(size_t)rowA * D + lane];
        float stB = st_buf[(size_t)rowB * D + lane];

        // layernorm over D (both rows)
        float mA = stA, mB = stB;
#pragma unroll
        for (int off = 16; off; off >>= 1) {
            mA += __shfl_xor_sync(FULLMASK, mA, off);
            mB += __shfl_xor_sync(FULLMASK, mB, off);
        }
        mA *= (1.f / 32.f); mB *= (1.f / 32.f);
        float dA = stA - mA, dB = stB - mB;
        float vA = dA * dA, vB = dB * dB;
#pragma unroll
        for (int off = 16; off; off >>= 1) {
            vA += __shfl_xor_sync(FULLMASK, vA, off);
            vB += __shfl_xor_sync(FULLMASK, vB, off);
        }
        vA *= (1.f / 32.f); vB *= (1.f / 32.f);
        float nxA = sg[lane] * dA * rsqrtf(vA + 1e-6f) + sb[lane];
        float nxB = sg[lane] * dB * rsqrtf(vB + 1e-6f) + sb[lane];

        // gates for both rows; weight LDS shared
        float giA = sbi[lane], gfA = sbi[32 + lane], ggA = sbi[64 + lane];
        float giB = giA, gfB = gfA, ggB = ggA;
#pragma unroll
        for (int d = 0; d < D; d++) {
            float avA = __shfl_sync(FULLMASK, aggA, d);
            float avB = __shfl_sync(FULLMASK, aggB, d);
            float wi = ihT[d * 128 + lane];
            float wf = ihT[d * 128 + 32 + lane];
            float wg = ihT[d * 128 + 64 + lane];
            giA = fmaf(avA, wi, giA); giB = fmaf(avB, wi, giB);
            gfA = fmaf(avA, wf, gfA); gfB = fmaf(avB, wf, gfB);
            ggA = fmaf(avA, wg, ggA); ggB = fmaf(avB, wg, ggB);
        }
        float igA = 1.f / (1.f + __expf(-giA));
        float fgA = 1.f / (1.f + __expf(-gfA));
        float gtA = tanhf(ggA);
        float igB = 1.f / (1.f + __expf(-giB));
        float fgB = 1.f / (1.f + __expf(-gfB));
        float gtB = tanhf(ggB);
        float outA = stA + fgA * nxA + igA * gtA;
        float outB = stB + fgB * nxB + igB * gtB;

        // final matmul, weight LDS shared
        float rA = sb2[lane], rB = rA;
#pragma unroll
        for (int d = 0; d < D; d++) {
            float w = w2T[d * D + lane];
            rA = fmaf(__shfl_sync(FULLMASK, outA, d), w, rA);
            rB = fmaf(__shfl_sync(FULLMASK, outB, d), w, rB);
        }
        out[(size_t)rowA * D + lane] = rA;
        out[(size_t)rowB * D + lane] = rB;
    }
}

// ---------------- launch ----------------
extern "C" void kernel_launch(void* const* d_in, const int* in_sizes, int n_in,
                              void* d_out, int out_size) {
    const float* state   = (const float*)d_in[0];
    const float* left    = (const float*)d_in[1];
    const float* inputad = (const float*)d_in[2];
    const float* w3      = (const float*)d_in[3];
    const float* b3      = (const float*)d_in[4];
    const float* attn_w  = (const float*)d_in[5];
    const float* w4      = (const float*)d_in[6];
    const float* b4      = (const float*)d_in[7];
    const float* w1      = (const float*)d_in[8];
    const float* b1      = (const float*)d_in[9];
    const float* w_ih    = (const float*)d_in[10];
    // d_in[11] = w_hh (unused by the reference except via b_hh)
    const float* b_ih    = (const float*)d_in[12];
    const float* b_hh    = (const float*)d_in[13];
    const float* ln_g    = (const float*)d_in[14];
    const float* ln_b    = (const float*)d_in[15];
    const float* w2      = (const float*)d_in[16];
    const float* b2      = (const float*)d_in[17];
    float* out = (float*)d_out;

    k1_gsl  <<<GRID_P, 256>>>(state, left, w3, b3, attn_w);   // launch 0
    k1b_prep<<<512, 256>>>(w4);                               // launch 1
    k1c_zero<<<2, 256>>>();                                   // launch 2 (csum=0)
    k2_fused<<<GRID_P, 256>>>(inputad, b4);                   // launch 3 -> profiled
    k3b_st  <<<GRID_P, 256>>>(w1, b1);
    k4_final<<<GRID_P, 256>>>(w_ih, b_ih, b_hh, ln_g, ln_b, w2, b2, out);
}